// round 4
// baseline (speedup 1.0000x reference)
#include <cuda_runtime.h>
#include <math.h>

#define NN   16000
#define EE   400000
#define FF   500
#define HH   256
#define CC   64
#define DINN 1268

// ---------------- scratch (static device allocations) ----------------
__device__ float g_T[(size_t)NN * FF];
__device__ float g_Z[(size_t)NN * HH];
__device__ float g_AGG[(size_t)NN * HH];
__device__ float g_HCAT[(size_t)NN * DINN];
__device__ float g_dinv[NN];
__device__ int   g_degi[NN];
__device__ int   g_rowptr[NN];
__device__ int   g_wofs[NN];
__device__ int   g_csr[EE];
__device__ float g_msum[HH];
__device__ float g_msq[HH];
__device__ float g_zerobias[CC];

// ---------------- small kernels ----------------
__global__ void init_kernel() {
    int n = blockIdx.x * blockDim.x + threadIdx.x;
    if (n < NN) { g_degi[n] = 0; g_wofs[n] = 0; }
    if (n < CC) g_zerobias[n] = 0.f;
}

__global__ void hist_kernel(const int* __restrict__ dst) {
    int e = blockIdx.x * blockDim.x + threadIdx.x;
    if (e < EE) atomicAdd(&g_degi[dst[e]], 1);
}

__global__ void dinv_kernel() {
    int n = blockIdx.x * blockDim.x + threadIdx.x;
    if (n < NN) g_dinv[n] = rsqrtf((float)(g_degi[n] + 1)); // +1 self loop
}

__global__ void scan_kernel() {  // exclusive scan of g_degi -> g_rowptr
    __shared__ int sh[1024];
    int tid = threadIdx.x;
    int base = tid * 16;
    int loc[16]; int s = 0;
#pragma unroll
    for (int i = 0; i < 16; i++) {
        int idx = base + i;
        int v = (idx < NN) ? g_degi[idx] : 0;
        loc[i] = s; s += v;
    }
    sh[tid] = s;
    __syncthreads();
    for (int off = 1; off < 1024; off <<= 1) {
        int v = 0;
        if (tid >= off) v = sh[tid - off];
        __syncthreads();
        sh[tid] += v;
        __syncthreads();
    }
    int pre = (tid > 0) ? sh[tid - 1] : 0;
#pragma unroll
    for (int i = 0; i < 16; i++) {
        int idx = base + i;
        if (idx < NN) g_rowptr[idx] = pre + loc[i];
    }
}

__global__ void scatter_kernel(const int* __restrict__ src, const int* __restrict__ dst) {
    int e = blockIdx.x * blockDim.x + threadIdx.x;
    if (e < EE) {
        int d = dst[e];
        int pos = g_rowptr[d] + atomicAdd(&g_wofs[d], 1);
        g_csr[pos] = src[e];
    }
}

__global__ void copyx_kernel(const float* __restrict__ x) {
    int idx = blockIdx.x * blockDim.x + threadIdx.x;
    if (idx < NN * FF) {
        int n = idx / FF, f = idx - n * FF;
        g_HCAT[(size_t)n * DINN + f] = x[idx];
    }
}

__global__ void bn_zero_kernel() {
    int c = threadIdx.x;
    g_msum[c] = 0.f; g_msq[c] = 0.f;
}

__global__ void bn_stats_kernel() {
    int c = threadIdx.x;
    int n0 = blockIdx.x * 128;
    float s = 0.f, s2 = 0.f;
#pragma unroll 4
    for (int r = 0; r < 128; r++) {
        float v = g_AGG[(size_t)(n0 + r) * HH + c];
        s += v; s2 += v * v;
    }
    atomicAdd(&g_msum[c], s);
    atomicAdd(&g_msq[c], s2);
}

__global__ void bn_apply_kernel(const float* __restrict__ bg, const float* __restrict__ bb, int off) {
    int n = blockIdx.x;
    int c = threadIdx.x;
    float mu = g_msum[c] * (1.0f / NN);
    float var = g_msq[c] * (1.0f / NN) - mu * mu;
    float rstd = rsqrtf(var + 1e-5f);
    float v = (g_AGG[(size_t)n * HH + c] - mu) * rstd * bg[c] + bb[c];
    g_HCAT[(size_t)n * DINN + off + c] = v;
}

// ---------------- GCN aggregation (CSR, no float atomics) ----------------
__global__ void aggregate_kernel(const float* __restrict__ cbias) {
    int n = blockIdx.x;
    int c = threadIdx.x;   // 256 channels
    __shared__ int ssrc[256];
    __shared__ float swt[256];
    float dn = g_dinv[n];
    float acc = g_Z[(size_t)n * HH + c] * dn * dn + cbias[c];  // self loop
    int start = g_rowptr[n];
    int cnt = g_degi[n];
    for (int base = 0; base < cnt; base += 256) {
        int e = base + c;
        if (e < cnt) {
            int s = g_csr[start + e];
            ssrc[c] = s;
            swt[c] = g_dinv[s] * dn;
        }
        __syncthreads();
        int lim = min(256, cnt - base);
#pragma unroll 4
        for (int q = 0; q < lim; q++)
            acc += g_Z[(size_t)ssrc[q] * HH + c] * swt[q];
        __syncthreads();
    }
    g_AGG[(size_t)n * HH + c] = acc;
}

// ---------------- fp32 GEMM: C[m][n] = act_out(sum_k act_in(A[m][k]) * W[n][k] + bias[n]) ----------------
template <int ACT_OUT /*1=gelu*/, int ACT_IN /*1=silu*/>
__global__ __launch_bounds__(256) void gemm_kernel(
    const float* __restrict__ A, int lda,
    const float* __restrict__ W,
    const float* __restrict__ bias,
    float* __restrict__ Cmat, int ldc,
    int K, int Nout)
{
    __shared__ float As[16][132];
    __shared__ float Ws[16][68];
    int tid = threadIdx.x;
    int tx = tid & 15, ty = tid >> 4;
    int bm = blockIdx.y * 128, bn = blockIdx.x * 64;

    float acc[8][4];
#pragma unroll
    for (int i = 0; i < 8; i++)
#pragma unroll
        for (int j = 0; j < 4; j++) acc[i][j] = 0.f;

    int ktn = (K + 15) >> 4;
    for (int kt = 0; kt < ktn; kt++) {
        int k0 = kt << 4;
#pragma unroll
        for (int r = 0; r < 8; r++) {
            int lin = tid + r * 256;
            int m = lin >> 4, k = lin & 15;
            int gk = k0 + k;
            float v = 0.f;
            if (gk < K) v = A[(size_t)(bm + m) * lda + gk];
            if (ACT_IN == 1) v = v / (1.f + __expf(-v));   // silu
            As[k][m] = v;
        }
#pragma unroll
        for (int r = 0; r < 4; r++) {
            int lin = tid + r * 256;
            int n = lin >> 4, k = lin & 15;
            int gk = k0 + k, gn = bn + n;
            float v = 0.f;
            if (gk < K && gn < Nout) v = W[(size_t)gn * K + gk];
            Ws[k][n] = v;
        }
        __syncthreads();
#pragma unroll
        for (int k = 0; k < 16; k++) {
            float4 wv = *(const float4*)&Ws[k][tx * 4];
            float4 a0 = *(const float4*)&As[k][ty * 8];
            float4 a1 = *(const float4*)&As[k][ty * 8 + 4];
            float av[8] = {a0.x, a0.y, a0.z, a0.w, a1.x, a1.y, a1.z, a1.w};
#pragma unroll
            for (int i = 0; i < 8; i++) {
                acc[i][0] += av[i] * wv.x;
                acc[i][1] += av[i] * wv.y;
                acc[i][2] += av[i] * wv.z;
                acc[i][3] += av[i] * wv.w;
            }
        }
        __syncthreads();
    }
#pragma unroll
    for (int i = 0; i < 8; i++) {
        int gm = bm + ty * 8 + i;
#pragma unroll
        for (int j = 0; j < 4; j++) {
            int gn = bn + tx * 4 + j;
            if (gn < Nout) {
                float v = acc[i][j] + bias[gn];
                if (ACT_OUT == 1)
                    v = 0.5f * v * (1.f + erff(v * 0.70710678118654752f)); // exact gelu
                Cmat[(size_t)gm * ldc + gn] = v;
            }
        }
    }
}

// ---------------- KAN spline branch ----------------
// out[n][o] += sum_{i,g} B_g(hcat[n][i]) * SW[o][i][g]
// Uniform cubic B-spline closed form (knot spacing 0.5, support [-2.5, 2.5)).
__global__ __launch_bounds__(256) void spline_kernel(const float* __restrict__ SW,
                                                     float* __restrict__ out)
{
    __shared__ float bs[28][132];
    __shared__ float ws[28][68];
    int tid = threadIdx.x;
    int tx = tid & 15, ty = tid >> 4;
    int bm = blockIdx.x * 128;

    float acc[8][4];
#pragma unroll
    for (int i = 0; i < 8; i++)
#pragma unroll
        for (int j = 0; j < 4; j++) acc[i][j] = 0.f;

    for (int i0 = 0; i0 < DINN; i0 += 4) {
#pragma unroll
        for (int r = 0; r < 2; r++) {
            int lin = tid + r * 256;
            int nloc = lin >> 2, ci = lin & 3;
            float z = g_HCAT[(size_t)(bm + nloc) * DINN + i0 + ci];
            int kkb = ci * 7;
#pragma unroll
            for (int g = 0; g < 7; g++) bs[kkb + g][nloc] = 0.f;
            float t = (z + 2.5f) * 2.0f;
            float jf = floorf(t);
            if (jf >= 0.f && jf <= 9.f) {
                float u = t - jf;
                float u2 = u * u, u3 = u2 * u;
                float om = 1.f - u;
                float b0 = om * om * om * (1.f / 6.f);
                float b1 = (3.f * u3 - 6.f * u2 + 4.f) * (1.f / 6.f);
                float b2 = (-3.f * u3 + 3.f * u2 + 3.f * u + 1.f) * (1.f / 6.f);
                float b3 = u3 * (1.f / 6.f);
                int j = (int)jf;
                int b = j - 3;
                if (b + 0 >= 0 && b + 0 < 7) bs[kkb + b + 0][nloc] = b0;
                if (b + 1 >= 0 && b + 1 < 7) bs[kkb + b + 1][nloc] = b1;
                if (b + 2 >= 0 && b + 2 < 7) bs[kkb + b + 2][nloc] = b2;
                if (b + 3 >= 0 && b + 3 < 7) bs[kkb + b + 3][nloc] = b3;
            }
        }
        {
            int o = tid >> 2, ci = tid & 3;
            const float* wp = SW + (size_t)o * (DINN * 7) + (size_t)(i0 + ci) * 7;
            int kkb = ci * 7;
#pragma unroll
            for (int g = 0; g < 7; g++) ws[kkb + g][o] = wp[g];
        }
        __syncthreads();
#pragma unroll
        for (int kk = 0; kk < 28; kk++) {
            float4 wv = *(const float4*)&ws[kk][tx * 4];
            float4 a0 = *(const float4*)&bs[kk][ty * 8];
            float4 a1 = *(const float4*)&bs[kk][ty * 8 + 4];
            float av[8] = {a0.x, a0.y, a0.z, a0.w, a1.x, a1.y, a1.z, a1.w};
#pragma unroll
            for (int i = 0; i < 8; i++) {
                acc[i][0] += av[i] * wv.x;
                acc[i][1] += av[i] * wv.y;
                acc[i][2] += av[i] * wv.z;
                acc[i][3] += av[i] * wv.w;
            }
        }
        __syncthreads();
    }
#pragma unroll
    for (int i = 0; i < 8; i++) {
        int gm = bm + ty * 8 + i;
#pragma unroll
        for (int j = 0; j < 4; j++) {
            int gn = tx * 4 + j;
            out[(size_t)gm * CC + gn] += acc[i][j];
        }
    }
}

// ---------------- launcher ----------------
extern "C" void kernel_launch(void* const* d_in, const int* in_sizes, int n_in,
                              void* d_out, int out_size)
{
    const float* x = (const float*)d_in[0];
    const float* base_w = (const float*)d_in[22];
    const float* spline_w = (const float*)d_in[23];
    const int* ei = (const int*)d_in[24];
    const int* srcA = ei;
    const int* dstA = ei + EE;
    float* out = (float*)d_out;

    float *pT, *pZ, *pHCAT, *pZB;
    cudaGetSymbolAddress((void**)&pT, g_T);
    cudaGetSymbolAddress((void**)&pZ, g_Z);
    cudaGetSymbolAddress((void**)&pHCAT, g_HCAT);
    cudaGetSymbolAddress((void**)&pZB, g_zerobias);

    init_kernel<<<(NN + 255) / 256, 256>>>();
    hist_kernel<<<(EE + 255) / 256, 256>>>(dstA);
    dinv_kernel<<<(NN + 255) / 256, 256>>>();
    scan_kernel<<<1, 1024>>>();
    scatter_kernel<<<(EE + 255) / 256, 256>>>(srcA, dstA);
    copyx_kernel<<<(NN * FF + 255) / 256, 256>>>(x);

    const int off_in[3]  = {0, FF, FF + HH};
    const int off_out[3] = {FF, FF + HH, FF + 2 * HH};

    for (int L = 0; L < 3; L++) {
        const float* w1 = (const float*)d_in[1 + 7 * L];
        const float* b1 = (const float*)d_in[2 + 7 * L];
        const float* w2 = (const float*)d_in[3 + 7 * L];
        const float* b2 = (const float*)d_in[4 + 7 * L];
        const float* cb = (const float*)d_in[5 + 7 * L];
        const float* bg = (const float*)d_in[6 + 7 * L];
        const float* bb = (const float*)d_in[7 + 7 * L];
        int fin = (L == 0) ? FF : HH;

        {   // fc1 + gelu -> T
            dim3 grid((fin + 63) / 64, NN / 128);
            gemm_kernel<1, 0><<<grid, 256>>>(pHCAT + off_in[L], DINN, w1, b1,
                                             pT, fin, fin, fin);
        }
        {   // fc2 -> Z
            dim3 grid((HH + 63) / 64, NN / 128);
            gemm_kernel<0, 0><<<grid, 256>>>(pT, fin, w2, b2, pZ, HH, fin, HH);
        }
        aggregate_kernel<<<NN, 256>>>(cb);
        bn_zero_kernel<<<1, 256>>>();
        bn_stats_kernel<<<NN / 128, 256>>>();
        bn_apply_kernel<<<NN, 256>>>(bg, bb, off_out[L]);
    }

    {   // KAN head base branch: silu(hcat) @ base_w^T -> out
        dim3 grid(1, NN / 128);
        gemm_kernel<0, 1><<<grid, 256>>>(pHCAT, DINN, base_w, pZB, out, CC, DINN, CC);
    }
    // spline branch accumulates into out
    spline_kernel<<<NN / 128, 256>>>(spline_w, out);
}

// round 16
// speedup vs baseline: 1.0504x; 1.0504x over previous
#include <cuda_runtime.h>
#include <cuda_bf16.h>
#include <math.h>
#include <stdint.h>

#define NN   16000
#define EE   400000
#define FF   500
#define HH   256
#define CC   64
#define DINN 1268
#define SPK  (DINN * 7)   // 8876

// ---------------- scratch (static device allocations) ----------------
__device__ float g_T[(size_t)NN * FF];
__device__ float g_Z[(size_t)NN * HH];
__device__ float g_AGG[(size_t)NN * HH];
__device__ float g_HCAT[(size_t)NN * DINN];
__device__ float g_dinv[NN];
__device__ int   g_degi[NN];
__device__ int   g_rowptr[NN];
__device__ int   g_wofs[NN];
__device__ int   g_csr[EE];
__device__ float g_msum[HH];
__device__ float g_msq[HH];
__device__ float g_zerobias[CC];

// ---------------- small kernels (unchanged, validated R4) ----------------
__global__ void init_kernel() {
    int n = blockIdx.x * blockDim.x + threadIdx.x;
    if (n < NN) { g_degi[n] = 0; g_wofs[n] = 0; }
    if (n < CC) g_zerobias[n] = 0.f;
}

__global__ void hist_kernel(const int* __restrict__ dst) {
    int e = blockIdx.x * blockDim.x + threadIdx.x;
    if (e < EE) atomicAdd(&g_degi[dst[e]], 1);
}

__global__ void dinv_kernel() {
    int n = blockIdx.x * blockDim.x + threadIdx.x;
    if (n < NN) g_dinv[n] = rsqrtf((float)(g_degi[n] + 1));
}

__global__ void scan_kernel() {
    __shared__ int sh[1024];
    int tid = threadIdx.x;
    int base = tid * 16;
    int loc[16]; int s = 0;
#pragma unroll
    for (int i = 0; i < 16; i++) {
        int idx = base + i;
        int v = (idx < NN) ? g_degi[idx] : 0;
        loc[i] = s; s += v;
    }
    sh[tid] = s;
    __syncthreads();
    for (int off = 1; off < 1024; off <<= 1) {
        int v = 0;
        if (tid >= off) v = sh[tid - off];
        __syncthreads();
        sh[tid] += v;
        __syncthreads();
    }
    int pre = (tid > 0) ? sh[tid - 1] : 0;
#pragma unroll
    for (int i = 0; i < 16; i++) {
        int idx = base + i;
        if (idx < NN) g_rowptr[idx] = pre + loc[i];
    }
}

__global__ void scatter_kernel(const int* __restrict__ src, const int* __restrict__ dst) {
    int e = blockIdx.x * blockDim.x + threadIdx.x;
    if (e < EE) {
        int d = dst[e];
        int pos = g_rowptr[d] + atomicAdd(&g_wofs[d], 1);
        g_csr[pos] = src[e];
    }
}

__global__ void copyx_kernel(const float* __restrict__ x) {
    int idx = blockIdx.x * blockDim.x + threadIdx.x;
    if (idx < NN * FF) {
        int n = idx / FF, f = idx - n * FF;
        g_HCAT[(size_t)n * DINN + f] = x[idx];
    }
}

__global__ void bn_zero_kernel() {
    int c = threadIdx.x;
    g_msum[c] = 0.f; g_msq[c] = 0.f;
}

__global__ void bn_stats_kernel() {
    int c = threadIdx.x;
    int n0 = blockIdx.x * 128;
    float s = 0.f, s2 = 0.f;
#pragma unroll 4
    for (int r = 0; r < 128; r++) {
        float v = g_AGG[(size_t)(n0 + r) * HH + c];
        s += v; s2 += v * v;
    }
    atomicAdd(&g_msum[c], s);
    atomicAdd(&g_msq[c], s2);
}

__global__ void bn_apply_kernel(const float* __restrict__ bg, const float* __restrict__ bb, int off) {
    int n = blockIdx.x;
    int c = threadIdx.x;
    float mu = g_msum[c] * (1.0f / NN);
    float var = g_msq[c] * (1.0f / NN) - mu * mu;
    float rstd = rsqrtf(var + 1e-5f);
    float v = (g_AGG[(size_t)n * HH + c] - mu) * rstd * bg[c] + bb[c];
    g_HCAT[(size_t)n * DINN + off + c] = v;
}

__global__ void aggregate_kernel(const float* __restrict__ cbias) {
    int n = blockIdx.x;
    int c = threadIdx.x;
    __shared__ int ssrc[256];
    __shared__ float swt[256];
    float dn = g_dinv[n];
    float acc = g_Z[(size_t)n * HH + c] * dn * dn + cbias[c];
    int start = g_rowptr[n];
    int cnt = g_degi[n];
    for (int base = 0; base < cnt; base += 256) {
        int e = base + c;
        if (e < cnt) {
            int s = g_csr[start + e];
            ssrc[c] = s;
            swt[c] = g_dinv[s] * dn;
        }
        __syncthreads();
        int lim = min(256, cnt - base);
#pragma unroll 4
        for (int q = 0; q < lim; q++)
            acc += g_Z[(size_t)ssrc[q] * HH + c] * swt[q];
        __syncthreads();
    }
    g_AGG[(size_t)n * HH + c] = acc;
}

// ---------------- MMA helpers ----------------
__device__ __forceinline__ uint32_t smem_u32(const void* p) {
    return (uint32_t)__cvta_generic_to_shared(p);
}

__device__ __forceinline__ void ldm_x4(uint32_t* r, uint32_t addr) {
    asm volatile("ldmatrix.sync.aligned.m8n8.x4.shared.b16 {%0,%1,%2,%3}, [%4];"
                 : "=r"(r[0]), "=r"(r[1]), "=r"(r[2]), "=r"(r[3]) : "r"(addr));
}

__device__ __forceinline__ void mma16816(float* c, const uint32_t* a, uint32_t b0, uint32_t b1) {
    asm volatile(
        "mma.sync.aligned.m16n8k16.row.col.f32.bf16.bf16.f32 "
        "{%0,%1,%2,%3}, {%4,%5,%6,%7}, {%8,%9}, {%0,%1,%2,%3};"
        : "+f"(c[0]), "+f"(c[1]), "+f"(c[2]), "+f"(c[3])
        : "r"(a[0]), "r"(a[1]), "r"(a[2]), "r"(a[3]), "r"(b0), "r"(b1));
}

// split a float pair into packed bf16 hi and lo words
__device__ __forceinline__ void split2(float x, float y, uint32_t& hi, uint32_t& lo) {
    __nv_bfloat16 hx = __float2bfloat16(x);
    __nv_bfloat16 hy = __float2bfloat16(y);
    __nv_bfloat16 lx = __float2bfloat16(x - __bfloat162float(hx));
    __nv_bfloat16 ly = __float2bfloat16(y - __bfloat162float(hy));
    __nv_bfloat162 h2 = __halves2bfloat162(hx, hy);
    __nv_bfloat162 l2 = __halves2bfloat162(lx, ly);
    hi = *(uint32_t*)&h2;
    lo = *(uint32_t*)&l2;
}

#define LDK 40   // smem row length (bf16 elems): 80B stride, conflict-free for ldmatrix

// ---------------- split-bf16 tensor-core GEMM ----------------
// C[m][n] = act_out( sum_k act_in(A[m][k]) * W[n][k] + bias[n] )
// BM=128, BN=64, BK=32, 256 threads (8 warps, 4x2), warp tile 32x32.
template <int ACT_OUT /*1=gelu*/, int ACT_IN /*1=silu*/>
__global__ __launch_bounds__(256) void mma_gemm_kernel(
    const float* __restrict__ A, int lda,
    const float* __restrict__ W,
    const float* __restrict__ bias,
    float* __restrict__ Cmat, int ldc,
    int K, int Nout)
{
    __shared__ __align__(16) __nv_bfloat16 As[2][128][LDK];
    __shared__ __align__(16) __nv_bfloat16 Ws[2][64][LDK];

    int tid = threadIdx.x;
    int lane = tid & 31, warp = tid >> 5;
    int wm = warp & 3, wn = warp >> 2;          // warp origin (wm*32, wn*32)
    int bm = blockIdx.y * 128, bn = blockIdx.x * 64;

    float acc[2][4][4];
#pragma unroll
    for (int i = 0; i < 2; i++)
#pragma unroll
        for (int j = 0; j < 4; j++)
#pragma unroll
            for (int l = 0; l < 4; l++) acc[i][j][l] = 0.f;

    int arow = tid >> 1, akh = (tid & 1) * 16;  // A loader: 16 floats per thread
    int wrow = tid >> 2, wkq = (tid & 3) * 8;   // W loader: 8 floats per thread

    for (int k0 = 0; k0 < K; k0 += 32) {
        // ---- load + split A tile [128][32] ----
#pragma unroll
        for (int q = 0; q < 4; q++) {
            int gk = k0 + akh + q * 4;
            float4 v = make_float4(0.f, 0.f, 0.f, 0.f);
            if (gk < K) v = *(const float4*)(A + (size_t)(bm + arow) * lda + gk);
            if (ACT_IN == 1) {
                v.x = v.x / (1.f + __expf(-v.x));
                v.y = v.y / (1.f + __expf(-v.y));
                v.z = v.z / (1.f + __expf(-v.z));
                v.w = v.w / (1.f + __expf(-v.w));
            }
            uint32_t h0, l0, h1, l1;
            split2(v.x, v.y, h0, l0);
            split2(v.z, v.w, h1, l1);
            int kk = akh + q * 4;
            *(uint32_t*)&As[0][arow][kk]     = h0;
            *(uint32_t*)&As[0][arow][kk + 2] = h1;
            *(uint32_t*)&As[1][arow][kk]     = l0;
            *(uint32_t*)&As[1][arow][kk + 2] = l1;
        }
        // ---- load + split W tile [64][32] ----
#pragma unroll
        for (int q = 0; q < 2; q++) {
            int gk = k0 + wkq + q * 4;
            int gn = bn + wrow;
            float4 v = make_float4(0.f, 0.f, 0.f, 0.f);
            if (gn < Nout && gk < K) v = *(const float4*)(W + (size_t)gn * K + gk);
            uint32_t h0, l0, h1, l1;
            split2(v.x, v.y, h0, l0);
            split2(v.z, v.w, h1, l1);
            int kk = wkq + q * 4;
            *(uint32_t*)&Ws[0][wrow][kk]     = h0;
            *(uint32_t*)&Ws[0][wrow][kk + 2] = h1;
            *(uint32_t*)&Ws[1][wrow][kk]     = l0;
            *(uint32_t*)&Ws[1][wrow][kk + 2] = l1;
        }
        __syncthreads();

        // ---- MMA: two k16 steps ----
#pragma unroll
        for (int ks = 0; ks < 32; ks += 16) {
            uint32_t afr[2][2][4];   // [split][mfrag]
            uint32_t bfr[2][2][4];   // [split][nfrag-pair]
#pragma unroll
            for (int s = 0; s < 2; s++) {
#pragma unroll
                for (int mf = 0; mf < 2; mf++) {
                    int r = wm * 32 + mf * 16 + (lane & 15);
                    int kc = ks + (lane >> 4) * 8;
                    ldm_x4(afr[s][mf], smem_u32(&As[s][r][kc]));
                }
#pragma unroll
                for (int pr = 0; pr < 2; pr++) {
                    int r = wn * 32 + pr * 16 + (lane & 7) + ((lane >> 4) & 1) * 8;
                    int kc = ks + ((lane >> 3) & 1) * 8;
                    ldm_x4(bfr[s][pr], smem_u32(&Ws[s][r][kc]));
                }
            }
#pragma unroll
            for (int mf = 0; mf < 2; mf++) {
#pragma unroll
                for (int nf = 0; nf < 4; nf++) {
                    uint32_t bh0 = bfr[0][nf >> 1][(nf & 1) * 2];
                    uint32_t bh1 = bfr[0][nf >> 1][(nf & 1) * 2 + 1];
                    uint32_t bl0 = bfr[1][nf >> 1][(nf & 1) * 2];
                    uint32_t bl1 = bfr[1][nf >> 1][(nf & 1) * 2 + 1];
                    mma16816(acc[mf][nf], afr[0][mf], bh0, bh1);  // hi*hi
                    mma16816(acc[mf][nf], afr[0][mf], bl0, bl1);  // hi*lo
                    mma16816(acc[mf][nf], afr[1][mf], bh0, bh1);  // lo*hi
                }
            }
        }
        __syncthreads();
    }

    // ---- epilogue ----
    int g = lane >> 2, tig = lane & 3;
#pragma unroll
    for (int mf = 0; mf < 2; mf++) {
        int r0 = bm + wm * 32 + mf * 16 + g;
#pragma unroll
        for (int nf = 0; nf < 4; nf++) {
            int col = bn + wn * 32 + nf * 8 + tig * 2;
            if (col < Nout) {
                float b0 = bias[col], b1 = bias[col + 1];
                float v0 = acc[mf][nf][0] + b0;
                float v1 = acc[mf][nf][1] + b1;
                float v2 = acc[mf][nf][2] + b0;
                float v3 = acc[mf][nf][3] + b1;
                if (ACT_OUT == 1) {
                    v0 = 0.5f * v0 * (1.f + erff(v0 * 0.70710678118654752f));
                    v1 = 0.5f * v1 * (1.f + erff(v1 * 0.70710678118654752f));
                    v2 = 0.5f * v2 * (1.f + erff(v2 * 0.70710678118654752f));
                    v3 = 0.5f * v3 * (1.f + erff(v3 * 0.70710678118654752f));
                }
                *(float2*)(Cmat + (size_t)r0 * ldc + col)       = make_float2(v0, v1);
                *(float2*)(Cmat + (size_t)(r0 + 8) * ldc + col) = make_float2(v2, v3);
            }
        }
    }
}

// ---------------- spline branch as split-bf16 MMA GEMM ----------------
// out[n][o] += sum_{k=i*7+g} S(2*(z[n][i]+2.5) - g) * SW[o][k],  K = 8876
__global__ __launch_bounds__(256) void spline_mma_kernel(
    const float* __restrict__ SW,
    float* __restrict__ out)
{
    __shared__ __align__(16) __nv_bfloat16 As[2][128][LDK];
    __shared__ __align__(16) __nv_bfloat16 Ws[2][64][LDK];
    __shared__ float zs[128][8];

    int tid = threadIdx.x;
    int lane = tid & 31, warp = tid >> 5;
    int wm = warp & 3, wn = warp >> 2;
    int bm = blockIdx.x * 128;

    float acc[2][4][4];
#pragma unroll
    for (int i = 0; i < 2; i++)
#pragma unroll
        for (int j = 0; j < 4; j++)
#pragma unroll
            for (int l = 0; l < 4; l++) acc[i][j][l] = 0.f;

    int wrow = tid >> 2, wkq = (tid & 3) * 8;
    int gencol = tid & 31;           // this thread's k column
    int genrow = (tid >> 5) * 16;    // 16 rows per thread

    for (int k0 = 0; k0 < SPK; k0 += 32) {
        int i0 = k0 / 7;
        // ---- load z tile [128][6] ----
#pragma unroll
        for (int q = 0; q < 3; q++) {
            int idx = tid + q * 256;
            int n = idx / 6, ii = idx - n * 6;
            int gi = i0 + ii;
            zs[n][ii] = (gi < DINN) ? g_HCAT[(size_t)(bm + n) * DINN + gi] : 0.f;
        }
        // ---- load + split SW tile ----
#pragma unroll
        for (int q = 0; q < 2; q++) {
            int gk = k0 + wkq + q * 4;
            float4 v = make_float4(0.f, 0.f, 0.f, 0.f);
            if (gk < SPK) v = *(const float4*)(SW + (size_t)wrow * SPK + gk);
            uint32_t h0, l0, h1, l1;
            split2(v.x, v.y, h0, l0);
            split2(v.z, v.w, h1, l1);
            int kk = wkq + q * 4;
            *(uint32_t*)&Ws[0][wrow][kk]     = h0;
            *(uint32_t*)&Ws[0][wrow][kk + 2] = h1;
            *(uint32_t*)&Ws[1][wrow][kk]     = l0;
            *(uint32_t*)&Ws[1][wrow][kk + 2] = l1;
        }
        __syncthreads();   // zs ready

        // ---- generate basis tile As[.][128][32] ----
        {
            int k = k0 + gencol;
            int i = k / 7;
            int gb = k - i * 7;
            bool kvalid = (k < SPK);
            int zi = i - i0;
#pragma unroll
            for (int r = 0; r < 16; r++) {
                float z = zs[genrow + r][zi];
                float t = (z + 2.5f) * 2.0f;
                float s = t - (float)gb;
                float val = 0.f;
                if (kvalid && s > 0.f && s < 4.f) {
                    int fs = (int)s;
                    float u = s - (float)fs;
                    float p;
                    if (fs == 0)      p = u * u * u * (1.f / 6.f);
                    else if (fs == 1) p = (-3.f * u * u * u + 3.f * u * u + 3.f * u + 1.f) * (1.f / 6.f);
                    else if (fs == 2) p = (3.f * u * u * u - 6.f * u * u + 4.f) * (1.f / 6.f);
                    else              { float om = 1.f - u; p = om * om * om * (1.f / 6.f); }
                    val = p;
                }
                __nv_bfloat16 h = __float2bfloat16(val);
                __nv_bfloat16 l = __float2bfloat16(val - __bfloat162float(h));
                As[0][genrow + r][gencol] = h;
                As[1][genrow + r][gencol] = l;
            }
        }
        __syncthreads();   // As/Ws ready

        // ---- MMA ----
#pragma unroll
        for (int ks = 0; ks < 32; ks += 16) {
            uint32_t afr[2][2][4];
            uint32_t bfr[2][2][4];
#pragma unroll
            for (int s = 0; s < 2; s++) {
#pragma unroll
                for (int mf = 0; mf < 2; mf++) {
                    int r = wm * 32 + mf * 16 + (lane & 15);
                    int kc = ks + (lane >> 4) * 8;
                    ldm_x4(afr[s][mf], smem_u32(&As[s][r][kc]));
                }
#pragma unroll
                for (int pr = 0; pr < 2; pr++) {
                    int r = wn * 32 + pr * 16 + (lane & 7) + ((lane >> 4) & 1) * 8;
                    int kc = ks + ((lane >> 3) & 1) * 8;
                    ldm_x4(bfr[s][pr], smem_u32(&Ws[s][r][kc]));
                }
            }
#pragma unroll
            for (int mf = 0; mf < 2; mf++) {
#pragma unroll
                for (int nf = 0; nf < 4; nf++) {
                    uint32_t bh0 = bfr[0][nf >> 1][(nf & 1) * 2];
                    uint32_t bh1 = bfr[0][nf >> 1][(nf & 1) * 2 + 1];
                    uint32_t bl0 = bfr[1][nf >> 1][(nf & 1) * 2];
                    uint32_t bl1 = bfr[1][nf >> 1][(nf & 1) * 2 + 1];
                    mma16816(acc[mf][nf], afr[0][mf], bh0, bh1);
                    mma16816(acc[mf][nf], afr[0][mf], bl0, bl1);
                    mma16816(acc[mf][nf], afr[1][mf], bh0, bh1);
                }
            }
        }
        __syncthreads();
    }

    // ---- epilogue: accumulate into out ----
    int g = lane >> 2, tig = lane & 3;
#pragma unroll
    for (int mf = 0; mf < 2; mf++) {
        int r0 = bm + wm * 32 + mf * 16 + g;
#pragma unroll
        for (int nf = 0; nf < 4; nf++) {
            int col = wn * 32 + nf * 8 + tig * 2;
            float2* p0 = (float2*)(out + (size_t)r0 * CC + col);
            float2* p1 = (float2*)(out + (size_t)(r0 + 8) * CC + col);
            float2 v0 = *p0, v1 = *p1;
            v0.x += acc[mf][nf][0]; v0.y += acc[mf][nf][1];
            v1.x += acc[mf][nf][2]; v1.y += acc[mf][nf][3];
            *p0 = v0; *p1 = v1;
        }
    }
}

// ---------------- launcher ----------------
extern "C" void kernel_launch(void* const* d_in, const int* in_sizes, int n_in,
                              void* d_out, int out_size)
{
    const float* x = (const float*)d_in[0];
    const float* base_w = (const float*)d_in[22];
    const float* spline_w = (const float*)d_in[23];
    const int* ei = (const int*)d_in[24];
    const int* srcA = ei;
    const int* dstA = ei + EE;
    float* out = (float*)d_out;

    float *pT, *pZ, *pHCAT, *pZB;
    cudaGetSymbolAddress((void**)&pT, g_T);
    cudaGetSymbolAddress((void**)&pZ, g_Z);
    cudaGetSymbolAddress((void**)&pHCAT, g_HCAT);
    cudaGetSymbolAddress((void**)&pZB, g_zerobias);

    init_kernel<<<(NN + 255) / 256, 256>>>();
    hist_kernel<<<(EE + 255) / 256, 256>>>(dstA);
    dinv_kernel<<<(NN + 255) / 256, 256>>>();
    scan_kernel<<<1, 1024>>>();
    scatter_kernel<<<(EE + 255) / 256, 256>>>(srcA, dstA);
    copyx_kernel<<<(NN * FF + 255) / 256, 256>>>(x);

    const int off_in[3]  = {0, FF, FF + HH};
    const int off_out[3] = {FF, FF + HH, FF + 2 * HH};

    for (int L = 0; L < 3; L++) {
        const float* w1 = (const float*)d_in[1 + 7 * L];
        const float* b1 = (const float*)d_in[2 + 7 * L];
        const float* w2 = (const float*)d_in[3 + 7 * L];
        const float* b2 = (const float*)d_in[4 + 7 * L];
        const float* cb = (const float*)d_in[5 + 7 * L];
        const float* bg = (const float*)d_in[6 + 7 * L];
        const float* bb = (const float*)d_in[7 + 7 * L];
        int fin = (L == 0) ? FF : HH;

        {   // fc1 + gelu -> T
            dim3 grid((fin + 63) / 64, NN / 128);
            mma_gemm_kernel<1, 0><<<grid, 256>>>(pHCAT + off_in[L], DINN, w1, b1,
                                                 pT, fin, fin, fin);
        }
        {   // fc2 -> Z
            dim3 grid(HH / 64, NN / 128);
            mma_gemm_kernel<0, 0><<<grid, 256>>>(pT, fin, w2, b2, pZ, HH, fin, HH);
        }
        aggregate_kernel<<<NN, 256>>>(cb);
        bn_zero_kernel<<<1, 256>>>();
        bn_stats_kernel<<<NN / 128, 256>>>();
        bn_apply_kernel<<<NN, 256>>>(bg, bb, off_out[L]);
    }

    {   // KAN head base branch: silu(hcat) @ base_w^T -> out
        dim3 grid(1, NN / 128);
        mma_gemm_kernel<0, 1><<<grid, 256>>>(pHCAT, DINN, base_w, pZB, out, CC, DINN, CC);
    }
    // spline branch accumulates into out
    spline_mma_kernel<<<NN / 128, 256>>>(spline_w, out);
}